// round 15
// baseline (speedup 1.0000x reference)
#include <cuda_runtime.h>
#include <cuda_bf16.h>
#include <cuda_fp16.h>
#include <cstdint>

// Problem constants (shapes fixed by the reference)
#define NMAX   50000
#define EMAX   800000
#define IND    128        // IN_DIM
#define HD     128        // HEADS * D
#define HEADS  8
#define DDIM   16

// Scratch: Q fp32 (streamed once). K and V interleaved fp16:
//   g_KV[node*256 + g*8 + 0..3] = K dims 4g..4g+3
//   g_KV[node*256 + g*8 + 4..7] = V dims 4g..4g+3     (g = 0..31)
// Node stride = 256 halves = 512 bytes = 32 uint4.
__device__ float  g_Q[NMAX * HD];
__device__ __align__(16) __half g_KV[NMAX * HD * 2];

// CSR-by-dst build scratch.
// INVARIANTS at kernel_launch entry (BSS-zero initially, restored each call):
//   g_deg all-zero   (scan zeroes what it reads)
//   g_bflag all-zero (scatter resets after the scan consumed them)
__device__ int g_deg[NMAX];
__device__ int g_bsums[64];
__device__ int g_bflag[64];
__device__ int g_rowstart[NMAX + 1];
__device__ int g_cursor[NMAX];
__device__ int g_src_sorted[EMAX];

// ---------------------------------------------------------------------------
// FUSED QKV projection GEMM — fp16 MMA (m16n8k16, fp32 accumulate).
// (unchanged from R14 passing version)
// ---------------------------------------------------------------------------
#define PAD_H 136
#define GEMM_SMEM_BYTES (2 * 128 * PAD_H * 2)

__device__ __forceinline__ void mma_f16(float c[4],
                                        uint32_t a0, uint32_t a1,
                                        uint32_t a2, uint32_t a3,
                                        uint32_t b0, uint32_t b1) {
    asm volatile(
        "mma.sync.aligned.m16n8k16.row.col.f32.f16.f16.f32 "
        "{%0,%1,%2,%3}, {%4,%5,%6,%7}, {%8,%9}, {%0,%1,%2,%3};"
        : "+f"(c[0]), "+f"(c[1]), "+f"(c[2]), "+f"(c[3])
        : "r"(a0), "r"(a1), "r"(a2), "r"(a3), "r"(b0), "r"(b1));
}

__global__ __launch_bounds__(256)
void qkv_gemm_fused(const float* __restrict__ h,
                    const float* __restrict__ Wq, const float* __restrict__ bq,
                    const float* __restrict__ Wk, const float* __restrict__ bk,
                    const float* __restrict__ Wv, const float* __restrict__ bv,
                    int n_nodes)
{
    extern __shared__ __half smemh[];
    __half* as = smemh;                  // as[r*PAD_H + k]
    __half* ws = smemh + 128 * PAD_H;    // ws[n*PAD_H + k]  (W transposed)

    const int row0 = blockIdx.x * 128;
    const int tid  = threadIdx.x;

    const float* Wmat[3]  = {Wq, Wk, Wv};
    const float* Bvec[3]  = {bq, bk, bv};

    #pragma unroll
    for (int i = 0; i < 64; i++) {
        int lin = tid + i * 256;
        int r = lin >> 7;
        int k = lin & 127;
        float v = 0.0f;
        int gr = row0 + r;
        if (gr < n_nodes) v = h[gr * IND + k];
        as[r * PAD_H + k] = __float2half_rn(v);
    }
    {
        const float* W = Wmat[0];
        #pragma unroll
        for (int i = 0; i < 64; i++) {
            int lin = tid + i * 256;
            int k = lin >> 7;
            int n = lin & 127;
            ws[n * PAD_H + k] = __float2half_rn(W[k * HD + n]);
        }
    }
    __syncthreads();

    const int warp   = tid >> 5;
    const int lane   = tid & 31;
    const int g      = lane >> 2;       // 0..7
    const int t      = lane & 3;        // 0..3
    const int warp_m = warp & 3;        // 0..3
    const int warp_n = warp >> 2;       // 0..1

    const __half* a_base = as + (warp_m * 32 + g) * PAD_H + 2 * t;
    const __half* b_base = ws + (warp_n * 64 + g) * PAD_H + 2 * t;

    #pragma unroll
    for (int w = 0; w < 3; w++) {
        const float* bias = Bvec[w];

        float c[2][8][4];
        #pragma unroll
        for (int ni = 0; ni < 8; ni++) {
            int col = warp_n * 64 + ni * 8 + 2 * t;
            float b0 = bias[col];
            float b1 = bias[col + 1];
            #pragma unroll
            for (int mi = 0; mi < 2; mi++) {
                c[mi][ni][0] = b0; c[mi][ni][1] = b1;
                c[mi][ni][2] = b0; c[mi][ni][3] = b1;
            }
        }

        #pragma unroll
        for (int kk = 0; kk < 8; kk++) {
            const int k0 = kk * 16;

            uint32_t a[2][4];
            #pragma unroll
            for (int mi = 0; mi < 2; mi++) {
                const __half* ap = a_base + mi * 16 * PAD_H + k0;
                a[mi][0] = *(const uint32_t*)(ap);
                a[mi][1] = *(const uint32_t*)(ap + 8 * PAD_H);
                a[mi][2] = *(const uint32_t*)(ap + 8);
                a[mi][3] = *(const uint32_t*)(ap + 8 * PAD_H + 8);
            }

            uint32_t b[8][2];
            #pragma unroll
            for (int ni = 0; ni < 8; ni++) {
                const __half* bp = b_base + ni * 8 * PAD_H + k0;
                b[ni][0] = *(const uint32_t*)(bp);
                b[ni][1] = *(const uint32_t*)(bp + 8);
            }

            #pragma unroll
            for (int mi = 0; mi < 2; mi++)
                #pragma unroll
                for (int ni = 0; ni < 8; ni++)
                    mma_f16(c[mi][ni], a[mi][0], a[mi][1], a[mi][2], a[mi][3],
                            b[ni][0], b[ni][1]);
        }

        if (w == 0) {
            #pragma unroll
            for (int mi = 0; mi < 2; mi++) {
                int r_lo = row0 + warp_m * 32 + mi * 16 + g;
                #pragma unroll
                for (int ni = 0; ni < 8; ni++) {
                    int col = warp_n * 64 + ni * 8 + 2 * t;
                    if (r_lo < n_nodes)
                        *(float2*)&g_Q[(size_t)r_lo * HD + col] =
                            make_float2(c[mi][ni][0], c[mi][ni][1]);
                    if (r_lo + 8 < n_nodes)
                        *(float2*)&g_Q[(size_t)(r_lo + 8) * HD + col] =
                            make_float2(c[mi][ni][2], c[mi][ni][3]);
                }
            }
        } else {
            const int kvofs = (w == 1) ? 0 : 4;  // K at 0..3, V at 4..7
            #pragma unroll
            for (int mi = 0; mi < 2; mi++) {
                int r_lo = row0 + warp_m * 32 + mi * 16 + g;
                #pragma unroll
                for (int ni = 0; ni < 8; ni++) {
                    int col = warp_n * 64 + ni * 8 + 2 * t;       // even
                    int ofs = (col >> 2) * 8 + (col & 3) + kvofs; // contiguous pair
                    if (r_lo < n_nodes)
                        *(__half2*)&g_KV[(size_t)r_lo * 256 + ofs] =
                            __floats2half2_rn(c[mi][ni][0], c[mi][ni][1]);
                    if (r_lo + 8 < n_nodes)
                        *(__half2*)&g_KV[(size_t)(r_lo + 8) * 256 + ofs] =
                            __floats2half2_rn(c[mi][ni][2], c[mi][ni][3]);
                }
            }
        }

        if (w < 2) {
            __syncthreads();
            const float* Wn = Wmat[w + 1];
            #pragma unroll
            for (int i = 0; i < 64; i++) {
                int lin = tid + i * 256;
                int k = lin >> 7;
                int n = lin & 127;
                ws[n * PAD_H + k] = __float2half_rn(Wn[k * HD + n]);
            }
            __syncthreads();
        }
    }
}

// ---------------------------------------------------------------------------
// hist: dst-degree histogram, 4 edges/thread via int4 (MLP=4 on the REDGs).
// ---------------------------------------------------------------------------
__global__ __launch_bounds__(256)
void hist_kernel(const int* __restrict__ dst, int n_edges)
{
    int q = blockIdx.x * blockDim.x + threadIdx.x;   // quad index
    int e0 = q * 4;
    if (e0 + 4 <= n_edges) {
        int4 d4 = __ldg((const int4*)(dst + e0));
        atomicAdd(&g_deg[d4.x], 1);
        atomicAdd(&g_deg[d4.y], 1);
        atomicAdd(&g_deg[d4.z], 1);
        atomicAdd(&g_deg[d4.w], 1);
    } else {
        for (int e = e0; e < n_edges; e++)
            atomicAdd(&g_deg[__ldg(dst + e)], 1);
    }
}

// ---------------------------------------------------------------------------
// scan_fused: single-pass global exclusive scan of g_deg (49 blocks, all
// co-resident on 148 SMs -> no deadlock). Each block:
//   1. local exclusive scan of its 1024 elements (zeroing g_deg behind it)
//   2. publishes its block total (threadfence + atomicExch flag)
//   3. spins (L1-bypassing atomicAdd) on all predecessor flags
//   4. sums predecessor totals, applies, emits rowstart + cursor
// Flags are reset by scatter_kernel (runs after in-stream) -> per-call
// invariant restored, fully deterministic.
// ---------------------------------------------------------------------------
__global__ __launch_bounds__(1024)
void scan_fused_kernel(int n, int n_edges)
{
    __shared__ int wsum[32];
    __shared__ int boff_s;
    int tid  = threadIdx.x;
    int lane = tid & 31, wid = tid >> 5;
    int b = blockIdx.x;
    int i = b * 1024 + tid;

    int v = 0;
    if (i < n) {
        v = g_deg[i];
        g_deg[i] = 0;                 // self-restore for the next call
    }
    int x = v;
    #pragma unroll
    for (int o = 1; o < 32; o <<= 1) {
        int y = __shfl_up_sync(0xffffffffu, x, o);
        if (lane >= o) x += y;
    }
    if (lane == 31) wsum[wid] = x;
    __syncthreads();
    if (wid == 0) {
        int w = wsum[lane];
        #pragma unroll
        for (int o = 1; o < 32; o <<= 1) {
            int y = __shfl_up_sync(0xffffffffu, w, o);
            if (lane >= o) w += y;
        }
        wsum[lane] = w;  // inclusive warp totals
    }
    __syncthreads();
    int woff = (wid > 0) ? wsum[wid - 1] : 0;
    int local_excl = woff + x - v;

    // Publish block total early.
    if (tid == 1023) {
        g_bsums[b] = woff + x;
        __threadfence();
        atomicExch(&g_bflag[b], 1);
    }

    // Wait for all predecessors (atomicAdd read bypasses L1).
    if (tid < b) {
        while (atomicAdd(&g_bflag[tid], 0) == 0) { }
    }
    __syncthreads();

    // Sum predecessor totals (warp 0).
    if (wid == 0) {
        int s = 0;
        for (int j = lane; j < b; j += 32) s += g_bsums[j];
        #pragma unroll
        for (int o = 16; o; o >>= 1) s += __shfl_xor_sync(0xffffffffu, s, o);
        if (lane == 0) boff_s = s;
    }
    __syncthreads();

    int r = local_excl + boff_s;
    if (i < n) {
        g_rowstart[i] = r;
        g_cursor[i]   = r;
    }
    if (i == n) g_rowstart[n] = n_edges;
}

// ---------------------------------------------------------------------------
// scatter: 4 edges/thread via int4 loads -> 4 independent ATOMGs in flight.
// Also resets the scan's lookback flags (runs strictly after the scan).
// ---------------------------------------------------------------------------
__global__ __launch_bounds__(256)
void scatter_kernel(const int* __restrict__ src, const int* __restrict__ dst,
                    int n_edges)
{
    if (blockIdx.x == 0 && threadIdx.x < 64)
        g_bflag[threadIdx.x] = 0;     // restore invariant for next call

    int q = blockIdx.x * blockDim.x + threadIdx.x;
    int e0 = q * 4;
    if (e0 + 4 <= n_edges) {
        int4 s4 = __ldg((const int4*)(src + e0));
        int4 d4 = __ldg((const int4*)(dst + e0));
        int p0 = atomicAdd(&g_cursor[d4.x], 1);
        int p1 = atomicAdd(&g_cursor[d4.y], 1);
        int p2 = atomicAdd(&g_cursor[d4.z], 1);
        int p3 = atomicAdd(&g_cursor[d4.w], 1);
        g_src_sorted[p0] = s4.x;
        g_src_sorted[p1] = s4.y;
        g_src_sorted[p2] = s4.z;
        g_src_sorted[p3] = s4.w;
    } else {
        for (int e = e0; e < n_edges; e++) {
            int pos = atomicAdd(&g_cursor[__ldg(dst + e)], 1);
            g_src_sorted[pos] = __ldg(src + e);
        }
    }
}

// ---------------------------------------------------------------------------
// Aggregation: TWO warps per destination node, no atomics.
// Warp pair splits the edge row in half; odd warp deposits its partial in
// smem, even warp combines and stores. Doubles node-level MLP and halves
// warp-level tail imbalance. One uint4 gather per (edge, lane) fetches both
// K and V chunks (interleaved layout, node stride 32 uint4).
// ---------------------------------------------------------------------------
__device__ __forceinline__ float4 h4lo(uint4 u) {   // K halves 0..3
    float2 a = __half22float2(*(__half2*)&u.x);
    float2 b = __half22float2(*(__half2*)&u.y);
    return make_float4(a.x, a.y, b.x, b.y);
}
__device__ __forceinline__ float4 h4hi(uint4 u) {   // V halves 4..7
    float2 a = __half22float2(*(__half2*)&u.z);
    float2 b = __half22float2(*(__half2*)&u.w);
    return make_float4(a.x, a.y, b.x, b.y);
}

__global__ __launch_bounds__(256)
void aggregate_kernel(float* __restrict__ out, int n_nodes)
{
    __shared__ float partial[4][128];   // one 128-float slot per warp pair

    int tid  = threadIdx.x;
    int warp = tid >> 5;      // 0..7
    int lane = tid & 31;
    int pair = warp >> 1;     // 0..3
    int half = warp & 1;
    int d = blockIdx.x * 4 + pair;

    const float4* Q4  = (const float4*)g_Q;
    const uint4*  KV4 = (const uint4*)g_KV;  // node stride: 32 uint4

    float4 q = make_float4(0.f, 0.f, 0.f, 0.f);
    int beg = 0, end = 0;
    if (d < n_nodes) {
        q = __ldg(&Q4[(size_t)d * 32 + lane]);
        int b0 = g_rowstart[d];
        int e0 = g_rowstart[d + 1];
        int degh = (e0 - b0 + 1) >> 1;
        beg = half ? (b0 + degh) : b0;
        end = half ? e0 : (b0 + degh);
    }

    float4 acc = make_float4(0.f, 0.f, 0.f, 0.f);

    int e = beg;
    for (; e + 8 <= end; e += 8) {
        int s[8];
        #pragma unroll
        for (int j = 0; j < 8; j++) s[j] = __ldg(g_src_sorted + e + j);

        uint4 kv[8];
        #pragma unroll
        for (int j = 0; j < 8; j++)
            kv[j] = __ldg(&KV4[(size_t)s[j] * 32 + lane]);

        float p[8];
        #pragma unroll
        for (int j = 0; j < 8; j++) {
            float4 k = h4lo(kv[j]);
            p[j] = k.x*q.x + k.y*q.y + k.z*q.z + k.w*q.w;
        }
        #pragma unroll
        for (int j = 0; j < 8; j++) p[j] += __shfl_xor_sync(0xffffffffu, p[j], 1);
        #pragma unroll
        for (int j = 0; j < 8; j++) p[j] += __shfl_xor_sync(0xffffffffu, p[j], 2);
        #pragma unroll
        for (int j = 0; j < 8; j++) {
            float pj = p[j] * 0.25f;             // 1/sqrt(16)
            float4 v = h4hi(kv[j]);
            acc.x += pj * v.x; acc.y += pj * v.y;
            acc.z += pj * v.z; acc.w += pj * v.w;
        }
    }
    for (; e + 4 <= end; e += 4) {
        int s0 = __ldg(g_src_sorted + e);
        int s1 = __ldg(g_src_sorted + e + 1);
        int s2 = __ldg(g_src_sorted + e + 2);
        int s3 = __ldg(g_src_sorted + e + 3);

        uint4 kv0 = __ldg(&KV4[(size_t)s0 * 32 + lane]);
        uint4 kv1 = __ldg(&KV4[(size_t)s1 * 32 + lane]);
        uint4 kv2 = __ldg(&KV4[(size_t)s2 * 32 + lane]);
        uint4 kv3 = __ldg(&KV4[(size_t)s3 * 32 + lane]);

        float4 k0 = h4lo(kv0), k1 = h4lo(kv1), k2 = h4lo(kv2), k3 = h4lo(kv3);

        float p0 = k0.x*q.x + k0.y*q.y + k0.z*q.z + k0.w*q.w;
        float p1 = k1.x*q.x + k1.y*q.y + k1.z*q.z + k1.w*q.w;
        float p2 = k2.x*q.x + k2.y*q.y + k2.z*q.z + k2.w*q.w;
        float p3 = k3.x*q.x + k3.y*q.y + k3.z*q.z + k3.w*q.w;

        p0 += __shfl_xor_sync(0xffffffffu, p0, 1);
        p1 += __shfl_xor_sync(0xffffffffu, p1, 1);
        p2 += __shfl_xor_sync(0xffffffffu, p2, 1);
        p3 += __shfl_xor_sync(0xffffffffu, p3, 1);
        p0 += __shfl_xor_sync(0xffffffffu, p0, 2);
        p1 += __shfl_xor_sync(0xffffffffu, p1, 2);
        p2 += __shfl_xor_sync(0xffffffffu, p2, 2);
        p3 += __shfl_xor_sync(0xffffffffu, p3, 2);
        p0 *= 0.25f; p1 *= 0.25f; p2 *= 0.25f; p3 *= 0.25f;

        float4 v0 = h4hi(kv0), v1 = h4hi(kv1), v2 = h4hi(kv2), v3 = h4hi(kv3);

        acc.x += p0*v0.x + p1*v1.x + p2*v2.x + p3*v3.x;
        acc.y += p0*v0.y + p1*v1.y + p2*v2.y + p3*v3.y;
        acc.z += p0*v0.z + p1*v1.z + p2*v2.z + p3*v3.z;
        acc.w += p0*v0.w + p1*v1.w + p2*v2.w + p3*v3.w;
    }
    for (; e < end; e++) {
        int s = __ldg(g_src_sorted + e);
        uint4 kv = __ldg(&KV4[(size_t)s * 32 + lane]);
        float4 k = h4lo(kv);
        float p = k.x*q.x + k.y*q.y + k.z*q.z + k.w*q.w;
        p += __shfl_xor_sync(0xffffffffu, p, 1);
        p += __shfl_xor_sync(0xffffffffu, p, 2);
        p *= 0.25f;
        float4 v = h4hi(kv);
        acc.x += p*v.x; acc.y += p*v.y; acc.z += p*v.z; acc.w += p*v.w;
    }

    // Combine halves: odd warp deposits, even warp adds and stores.
    if (half == 1) {
        float* ps = &partial[pair][lane * 4];
        ps[0] = acc.x; ps[1] = acc.y; ps[2] = acc.z; ps[3] = acc.w;
    }
    __syncthreads();
    if (half == 0 && d < n_nodes) {
        const float* ps = &partial[pair][lane * 4];
        acc.x += ps[0]; acc.y += ps[1]; acc.z += ps[2]; acc.w += ps[3];
        *(float4*)&out[(size_t)d * HD + lane * 4] = acc;
    }
}

// ---------------------------------------------------------------------------
// Launch. Two parallel branches inside the captured graph:
//   branch A (side stream): qkv_gemm_fused
//   branch B (main stream): hist -> scan_fused -> scatter
// joined before aggregate.
// ---------------------------------------------------------------------------
extern "C" void kernel_launch(void* const* d_in, const int* in_sizes, int n_in,
                              void* d_out, int out_size)
{
    const float* h   = (const float*)d_in[0];
    const int*   src = (const int*)  d_in[1];
    const int*   dst = (const int*)  d_in[2];
    const float* Wq  = (const float*)d_in[3];
    const float* bq  = (const float*)d_in[4];
    const float* Wk  = (const float*)d_in[5];
    const float* bk  = (const float*)d_in[6];
    const float* Wv  = (const float*)d_in[7];
    const float* bv  = (const float*)d_in[8];
    float* out = (float*)d_out;

    int n_nodes = in_sizes[0] / IND;   // 50000
    int n_edges = in_sizes[1];         // 800000

    cudaFuncSetAttribute(qkv_gemm_fused,
                         cudaFuncAttributeMaxDynamicSharedMemorySize,
                         GEMM_SMEM_BYTES);

    static cudaStream_t side = nullptr;
    static cudaEvent_t  evFork = nullptr, evGemm = nullptr;
    if (side == nullptr) {
        cudaStreamCreateWithFlags(&side, cudaStreamNonBlocking);
        cudaEventCreateWithFlags(&evFork, cudaEventDisableTiming);
        cudaEventCreateWithFlags(&evGemm, cudaEventDisableTiming);
    }

    // Fork: fused GEMM branch on side stream.
    cudaEventRecord(evFork, 0);
    cudaStreamWaitEvent(side, evFork, 0);
    int gb = (n_nodes + 127) / 128;
    qkv_gemm_fused<<<gb, 256, GEMM_SMEM_BYTES, side>>>(h, Wq, bq, Wk, bk,
                                                       Wv, bv, n_nodes);
    cudaEventRecord(evGemm, side);

    // CSR branch on main stream (concurrent with GEMM).
    int nquad = (n_edges + 3) / 4;
    int qb = (nquad + 255) / 256;
    hist_kernel<<<qb, 256>>>(dst, n_edges);

    int nb1 = (n_nodes + 1 + 1023) / 1024;         // 49 blocks, all co-resident
    scan_fused_kernel<<<nb1, 1024>>>(n_nodes, n_edges);

    scatter_kernel<<<qb, 256>>>(src, dst, n_edges);

    // Join: aggregate needs both branches.
    cudaStreamWaitEvent(0, evGemm, 0);
    int ablocks = (n_nodes + 3) / 4;               // 4 node-pairs per block
    aggregate_kernel<<<ablocks, 256>>>(out, n_nodes);
}

// round 16
// speedup vs baseline: 1.0868x; 1.0868x over previous
#include <cuda_runtime.h>
#include <cuda_bf16.h>
#include <cuda_fp16.h>
#include <cstdint>

// Problem constants (shapes fixed by the reference)
#define NMAX   50000
#define EMAX   800000
#define IND    128        // IN_DIM
#define HD     128        // HEADS * D
#define HEADS  8
#define DDIM   16

// Scratch: Q fp32 (streamed once). K and V interleaved fp16:
//   g_KV[node*256 + g*8 + 0..3] = K dims 4g..4g+3
//   g_KV[node*256 + g*8 + 4..7] = V dims 4g..4g+3     (g = 0..31)
// Node stride = 256 halves = 512 bytes = 32 uint4.
__device__ float  g_Q[NMAX * HD];
__device__ __align__(16) __half g_KV[NMAX * HD * 2];

// CSR-by-dst build scratch.
// INVARIANTS at kernel_launch entry (BSS-zero initially, restored each call):
//   g_deg all-zero   (scan zeroes what it reads)
//   g_bflag all-zero (scatter resets after the scan consumed them)
__device__ int g_deg[NMAX];
__device__ int g_bsums[64];
__device__ int g_bflag[64];
__device__ int g_rowstart[NMAX + 1];
__device__ int g_cursor[NMAX];
__device__ int g_src_sorted[EMAX];

// ---------------------------------------------------------------------------
// FUSED QKV projection GEMM — fp16 MMA (m16n8k16, fp32 accumulate).
// (unchanged from R14/R15 passing versions)
// ---------------------------------------------------------------------------
#define PAD_H 136
#define GEMM_SMEM_BYTES (2 * 128 * PAD_H * 2)

__device__ __forceinline__ void mma_f16(float c[4],
                                        uint32_t a0, uint32_t a1,
                                        uint32_t a2, uint32_t a3,
                                        uint32_t b0, uint32_t b1) {
    asm volatile(
        "mma.sync.aligned.m16n8k16.row.col.f32.f16.f16.f32 "
        "{%0,%1,%2,%3}, {%4,%5,%6,%7}, {%8,%9}, {%0,%1,%2,%3};"
        : "+f"(c[0]), "+f"(c[1]), "+f"(c[2]), "+f"(c[3])
        : "r"(a0), "r"(a1), "r"(a2), "r"(a3), "r"(b0), "r"(b1));
}

__global__ __launch_bounds__(256)
void qkv_gemm_fused(const float* __restrict__ h,
                    const float* __restrict__ Wq, const float* __restrict__ bq,
                    const float* __restrict__ Wk, const float* __restrict__ bk,
                    const float* __restrict__ Wv, const float* __restrict__ bv,
                    int n_nodes)
{
    extern __shared__ __half smemh[];
    __half* as = smemh;                  // as[r*PAD_H + k]
    __half* ws = smemh + 128 * PAD_H;    // ws[n*PAD_H + k]  (W transposed)

    const int row0 = blockIdx.x * 128;
    const int tid  = threadIdx.x;

    const float* Wmat[3]  = {Wq, Wk, Wv};
    const float* Bvec[3]  = {bq, bk, bv};

    #pragma unroll
    for (int i = 0; i < 64; i++) {
        int lin = tid + i * 256;
        int r = lin >> 7;
        int k = lin & 127;
        float v = 0.0f;
        int gr = row0 + r;
        if (gr < n_nodes) v = h[gr * IND + k];
        as[r * PAD_H + k] = __float2half_rn(v);
    }
    {
        const float* W = Wmat[0];
        #pragma unroll
        for (int i = 0; i < 64; i++) {
            int lin = tid + i * 256;
            int k = lin >> 7;
            int n = lin & 127;
            ws[n * PAD_H + k] = __float2half_rn(W[k * HD + n]);
        }
    }
    __syncthreads();

    const int warp   = tid >> 5;
    const int lane   = tid & 31;
    const int g      = lane >> 2;       // 0..7
    const int t      = lane & 3;        // 0..3
    const int warp_m = warp & 3;        // 0..3
    const int warp_n = warp >> 2;       // 0..1

    const __half* a_base = as + (warp_m * 32 + g) * PAD_H + 2 * t;
    const __half* b_base = ws + (warp_n * 64 + g) * PAD_H + 2 * t;

    #pragma unroll
    for (int w = 0; w < 3; w++) {
        const float* bias = Bvec[w];

        float c[2][8][4];
        #pragma unroll
        for (int ni = 0; ni < 8; ni++) {
            int col = warp_n * 64 + ni * 8 + 2 * t;
            float b0 = bias[col];
            float b1 = bias[col + 1];
            #pragma unroll
            for (int mi = 0; mi < 2; mi++) {
                c[mi][ni][0] = b0; c[mi][ni][1] = b1;
                c[mi][ni][2] = b0; c[mi][ni][3] = b1;
            }
        }

        #pragma unroll
        for (int kk = 0; kk < 8; kk++) {
            const int k0 = kk * 16;

            uint32_t a[2][4];
            #pragma unroll
            for (int mi = 0; mi < 2; mi++) {
                const __half* ap = a_base + mi * 16 * PAD_H + k0;
                a[mi][0] = *(const uint32_t*)(ap);
                a[mi][1] = *(const uint32_t*)(ap + 8 * PAD_H);
                a[mi][2] = *(const uint32_t*)(ap + 8);
                a[mi][3] = *(const uint32_t*)(ap + 8 * PAD_H + 8);
            }

            uint32_t b[8][2];
            #pragma unroll
            for (int ni = 0; ni < 8; ni++) {
                const __half* bp = b_base + ni * 8 * PAD_H + k0;
                b[ni][0] = *(const uint32_t*)(bp);
                b[ni][1] = *(const uint32_t*)(bp + 8);
            }

            #pragma unroll
            for (int mi = 0; mi < 2; mi++)
                #pragma unroll
                for (int ni = 0; ni < 8; ni++)
                    mma_f16(c[mi][ni], a[mi][0], a[mi][1], a[mi][2], a[mi][3],
                            b[ni][0], b[ni][1]);
        }

        if (w == 0) {
            #pragma unroll
            for (int mi = 0; mi < 2; mi++) {
                int r_lo = row0 + warp_m * 32 + mi * 16 + g;
                #pragma unroll
                for (int ni = 0; ni < 8; ni++) {
                    int col = warp_n * 64 + ni * 8 + 2 * t;
                    if (r_lo < n_nodes)
                        *(float2*)&g_Q[(size_t)r_lo * HD + col] =
                            make_float2(c[mi][ni][0], c[mi][ni][1]);
                    if (r_lo + 8 < n_nodes)
                        *(float2*)&g_Q[(size_t)(r_lo + 8) * HD + col] =
                            make_float2(c[mi][ni][2], c[mi][ni][3]);
                }
            }
        } else {
            const int kvofs = (w == 1) ? 0 : 4;  // K at 0..3, V at 4..7
            #pragma unroll
            for (int mi = 0; mi < 2; mi++) {
                int r_lo = row0 + warp_m * 32 + mi * 16 + g;
                #pragma unroll
                for (int ni = 0; ni < 8; ni++) {
                    int col = warp_n * 64 + ni * 8 + 2 * t;       // even
                    int ofs = (col >> 2) * 8 + (col & 3) + kvofs; // contiguous pair
                    if (r_lo < n_nodes)
                        *(__half2*)&g_KV[(size_t)r_lo * 256 + ofs] =
                            __floats2half2_rn(c[mi][ni][0], c[mi][ni][1]);
                    if (r_lo + 8 < n_nodes)
                        *(__half2*)&g_KV[(size_t)(r_lo + 8) * 256 + ofs] =
                            __floats2half2_rn(c[mi][ni][2], c[mi][ni][3]);
                }
            }
        }

        if (w < 2) {
            __syncthreads();
            const float* Wn = Wmat[w + 1];
            #pragma unroll
            for (int i = 0; i < 64; i++) {
                int lin = tid + i * 256;
                int k = lin >> 7;
                int n = lin & 127;
                ws[n * PAD_H + k] = __float2half_rn(Wn[k * HD + n]);
            }
            __syncthreads();
        }
    }
}

// ---------------------------------------------------------------------------
// hist: dst-degree histogram, 4 edges/thread via int4 (MLP=4 on the REDGs).
// ---------------------------------------------------------------------------
__global__ __launch_bounds__(256)
void hist_kernel(const int* __restrict__ dst, int n_edges)
{
    int q = blockIdx.x * blockDim.x + threadIdx.x;   // quad index
    int e0 = q * 4;
    if (e0 + 4 <= n_edges) {
        int4 d4 = __ldg((const int4*)(dst + e0));
        atomicAdd(&g_deg[d4.x], 1);
        atomicAdd(&g_deg[d4.y], 1);
        atomicAdd(&g_deg[d4.z], 1);
        atomicAdd(&g_deg[d4.w], 1);
    } else {
        for (int e = e0; e < n_edges; e++)
            atomicAdd(&g_deg[__ldg(dst + e)], 1);
    }
}

// ---------------------------------------------------------------------------
// scan_fused: single-pass global exclusive scan of g_deg (49 blocks, all
// co-resident on 148 SMs -> no deadlock). Kept from R15 (passed correctness,
// saves a launch). Flags reset by scatter_kernel -> per-call invariant.
// ---------------------------------------------------------------------------
__global__ __launch_bounds__(1024)
void scan_fused_kernel(int n, int n_edges)
{
    __shared__ int wsum[32];
    __shared__ int boff_s;
    int tid  = threadIdx.x;
    int lane = tid & 31, wid = tid >> 5;
    int b = blockIdx.x;
    int i = b * 1024 + tid;

    int v = 0;
    if (i < n) {
        v = g_deg[i];
        g_deg[i] = 0;                 // self-restore for the next call
    }
    int x = v;
    #pragma unroll
    for (int o = 1; o < 32; o <<= 1) {
        int y = __shfl_up_sync(0xffffffffu, x, o);
        if (lane >= o) x += y;
    }
    if (lane == 31) wsum[wid] = x;
    __syncthreads();
    if (wid == 0) {
        int w = wsum[lane];
        #pragma unroll
        for (int o = 1; o < 32; o <<= 1) {
            int y = __shfl_up_sync(0xffffffffu, w, o);
            if (lane >= o) w += y;
        }
        wsum[lane] = w;  // inclusive warp totals
    }
    __syncthreads();
    int woff = (wid > 0) ? wsum[wid - 1] : 0;
    int local_excl = woff + x - v;

    // Publish block total early.
    if (tid == 1023) {
        g_bsums[b] = woff + x;
        __threadfence();
        atomicExch(&g_bflag[b], 1);
    }

    // Wait for all predecessors (atomicAdd read bypasses L1).
    if (tid < b) {
        while (atomicAdd(&g_bflag[tid], 0) == 0) { }
    }
    __syncthreads();

    // Sum predecessor totals (warp 0).
    if (wid == 0) {
        int s = 0;
        for (int j = lane; j < b; j += 32) s += g_bsums[j];
        #pragma unroll
        for (int o = 16; o; o >>= 1) s += __shfl_xor_sync(0xffffffffu, s, o);
        if (lane == 0) boff_s = s;
    }
    __syncthreads();

    int r = local_excl + boff_s;
    if (i < n) {
        g_rowstart[i] = r;
        g_cursor[i]   = r;
    }
    if (i == n) g_rowstart[n] = n_edges;
}

// ---------------------------------------------------------------------------
// scatter: 4 edges/thread via int4 loads -> 4 independent ATOMGs in flight.
// Also resets the scan's lookback flags (runs strictly after the scan).
// ---------------------------------------------------------------------------
__global__ __launch_bounds__(256)
void scatter_kernel(const int* __restrict__ src, const int* __restrict__ dst,
                    int n_edges)
{
    if (blockIdx.x == 0 && threadIdx.x < 64)
        g_bflag[threadIdx.x] = 0;     // restore invariant for next call

    int q = blockIdx.x * blockDim.x + threadIdx.x;
    int e0 = q * 4;
    if (e0 + 4 <= n_edges) {
        int4 s4 = __ldg((const int4*)(src + e0));
        int4 d4 = __ldg((const int4*)(dst + e0));
        int p0 = atomicAdd(&g_cursor[d4.x], 1);
        int p1 = atomicAdd(&g_cursor[d4.y], 1);
        int p2 = atomicAdd(&g_cursor[d4.z], 1);
        int p3 = atomicAdd(&g_cursor[d4.w], 1);
        g_src_sorted[p0] = s4.x;
        g_src_sorted[p1] = s4.y;
        g_src_sorted[p2] = s4.z;
        g_src_sorted[p3] = s4.w;
    } else {
        for (int e = e0; e < n_edges; e++) {
            int pos = atomicAdd(&g_cursor[__ldg(dst + e)], 1);
            g_src_sorted[pos] = __ldg(src + e);
        }
    }
}

// ---------------------------------------------------------------------------
// Aggregation: ONE warp per destination node, no atomics.
// (REVERTED to the R14 passing version — the 2-warp split destroyed the
// 8-edge wide-MLP batches and coupled warps via __syncthreads; R15 regressed.)
// One uint4 gather per (edge, lane) fetches both K and V chunks.
// Node stride in uint4 units: 32 (256 halves).
// ---------------------------------------------------------------------------
__device__ __forceinline__ float4 h4lo(uint4 u) {   // K halves 0..3
    float2 a = __half22float2(*(__half2*)&u.x);
    float2 b = __half22float2(*(__half2*)&u.y);
    return make_float4(a.x, a.y, b.x, b.y);
}
__device__ __forceinline__ float4 h4hi(uint4 u) {   // V halves 4..7
    float2 a = __half22float2(*(__half2*)&u.z);
    float2 b = __half22float2(*(__half2*)&u.w);
    return make_float4(a.x, a.y, b.x, b.y);
}

__global__ __launch_bounds__(256)
void aggregate_kernel(float* __restrict__ out, int n_nodes)
{
    int gtid = blockIdx.x * blockDim.x + threadIdx.x;
    int d    = gtid >> 5;
    int lane = gtid & 31;
    if (d >= n_nodes) return;

    const float4* Q4  = (const float4*)g_Q;
    const uint4*  KV4 = (const uint4*)g_KV;  // node stride: 32 uint4 (256 half)

    float4 q = __ldg(&Q4[(size_t)d * 32 + lane]);
    int beg = g_rowstart[d];
    int end = g_rowstart[d + 1];

    float4 acc = make_float4(0.f, 0.f, 0.f, 0.f);

    int e = beg;
    for (; e + 8 <= end; e += 8) {
        int s[8];
        #pragma unroll
        for (int j = 0; j < 8; j++) s[j] = __ldg(g_src_sorted + e + j);

        uint4 kv[8];
        #pragma unroll
        for (int j = 0; j < 8; j++)
            kv[j] = __ldg(&KV4[(size_t)s[j] * 32 + lane]);

        float p[8];
        #pragma unroll
        for (int j = 0; j < 8; j++) {
            float4 k = h4lo(kv[j]);
            p[j] = k.x*q.x + k.y*q.y + k.z*q.z + k.w*q.w;
        }
        #pragma unroll
        for (int j = 0; j < 8; j++) p[j] += __shfl_xor_sync(0xffffffffu, p[j], 1);
        #pragma unroll
        for (int j = 0; j < 8; j++) p[j] += __shfl_xor_sync(0xffffffffu, p[j], 2);
        #pragma unroll
        for (int j = 0; j < 8; j++) {
            float pj = p[j] * 0.25f;             // 1/sqrt(16)
            float4 v = h4hi(kv[j]);
            acc.x += pj * v.x; acc.y += pj * v.y;
            acc.z += pj * v.z; acc.w += pj * v.w;
        }
    }
    for (; e + 4 <= end; e += 4) {
        int s0 = __ldg(g_src_sorted + e);
        int s1 = __ldg(g_src_sorted + e + 1);
        int s2 = __ldg(g_src_sorted + e + 2);
        int s3 = __ldg(g_src_sorted + e + 3);

        uint4 kv0 = __ldg(&KV4[(size_t)s0 * 32 + lane]);
        uint4 kv1 = __ldg(&KV4[(size_t)s1 * 32 + lane]);
        uint4 kv2 = __ldg(&KV4[(size_t)s2 * 32 + lane]);
        uint4 kv3 = __ldg(&KV4[(size_t)s3 * 32 + lane]);

        float4 k0 = h4lo(kv0), k1 = h4lo(kv1), k2 = h4lo(kv2), k3 = h4lo(kv3);

        float p0 = k0.x*q.x + k0.y*q.y + k0.z*q.z + k0.w*q.w;
        float p1 = k1.x*q.x + k1.y*q.y + k1.z*q.z + k1.w*q.w;
        float p2 = k2.x*q.x + k2.y*q.y + k2.z*q.z + k2.w*q.w;
        float p3 = k3.x*q.x + k3.y*q.y + k3.z*q.z + k3.w*q.w;

        p0 += __shfl_xor_sync(0xffffffffu, p0, 1);
        p1 += __shfl_xor_sync(0xffffffffu, p1, 1);
        p2 += __shfl_xor_sync(0xffffffffu, p2, 1);
        p3 += __shfl_xor_sync(0xffffffffu, p3, 1);
        p0 += __shfl_xor_sync(0xffffffffu, p0, 2);
        p1 += __shfl_xor_sync(0xffffffffu, p1, 2);
        p2 += __shfl_xor_sync(0xffffffffu, p2, 2);
        p3 += __shfl_xor_sync(0xffffffffu, p3, 2);
        p0 *= 0.25f; p1 *= 0.25f; p2 *= 0.25f; p3 *= 0.25f;

        float4 v0 = h4hi(kv0), v1 = h4hi(kv1), v2 = h4hi(kv2), v3 = h4hi(kv3);

        acc.x += p0*v0.x + p1*v1.x + p2*v2.x + p3*v3.x;
        acc.y += p0*v0.y + p1*v1.y + p2*v2.y + p3*v3.y;
        acc.z += p0*v0.z + p1*v1.z + p2*v2.z + p3*v3.z;
        acc.w += p0*v0.w + p1*v1.w + p2*v2.w + p3*v3.w;
    }
    for (; e < end; e++) {
        int s = __ldg(g_src_sorted + e);
        uint4 kv = __ldg(&KV4[(size_t)s * 32 + lane]);
        float4 k = h4lo(kv);
        float p = k.x*q.x + k.y*q.y + k.z*q.z + k.w*q.w;
        p += __shfl_xor_sync(0xffffffffu, p, 1);
        p += __shfl_xor_sync(0xffffffffu, p, 2);
        p *= 0.25f;
        float4 v = h4hi(kv);
        acc.x += p*v.x; acc.y += p*v.y; acc.z += p*v.z; acc.w += p*v.w;
    }

    *(float4*)&out[(size_t)d * HD + lane * 4] = acc;
}

// ---------------------------------------------------------------------------
// Launch. Two parallel branches inside the captured graph:
//   branch A (side stream): qkv_gemm_fused
//   branch B (main stream): hist -> scan_fused -> scatter
// joined before aggregate.
// ---------------------------------------------------------------------------
extern "C" void kernel_launch(void* const* d_in, const int* in_sizes, int n_in,
                              void* d_out, int out_size)
{
    const float* h   = (const float*)d_in[0];
    const int*   src = (const int*)  d_in[1];
    const int*   dst = (const int*)  d_in[2];
    const float* Wq  = (const float*)d_in[3];
    const float* bq  = (const float*)d_in[4];
    const float* Wk  = (const float*)d_in[5];
    const float* bk  = (const float*)d_in[6];
    const float* Wv  = (const float*)d_in[7];
    const float* bv  = (const float*)d_in[8];
    float* out = (float*)d_out;

    int n_nodes = in_sizes[0] / IND;   // 50000
    int n_edges = in_sizes[1];         // 800000

    cudaFuncSetAttribute(qkv_gemm_fused,
                         cudaFuncAttributeMaxDynamicSharedMemorySize,
                         GEMM_SMEM_BYTES);

    static cudaStream_t side = nullptr;
    static cudaEvent_t  evFork = nullptr, evGemm = nullptr;
    if (side == nullptr) {
        cudaStreamCreateWithFlags(&side, cudaStreamNonBlocking);
        cudaEventCreateWithFlags(&evFork, cudaEventDisableTiming);
        cudaEventCreateWithFlags(&evGemm, cudaEventDisableTiming);
    }

    // Fork: fused GEMM branch on side stream.
    cudaEventRecord(evFork, 0);
    cudaStreamWaitEvent(side, evFork, 0);
    int gb = (n_nodes + 127) / 128;
    qkv_gemm_fused<<<gb, 256, GEMM_SMEM_BYTES, side>>>(h, Wq, bq, Wk, bk,
                                                       Wv, bv, n_nodes);
    cudaEventRecord(evGemm, side);

    // CSR branch on main stream (concurrent with GEMM).
    int nquad = (n_edges + 3) / 4;
    int qb = (nquad + 255) / 256;
    hist_kernel<<<qb, 256>>>(dst, n_edges);

    int nb1 = (n_nodes + 1 + 1023) / 1024;         // 49 blocks, all co-resident
    scan_fused_kernel<<<nb1, 1024>>>(n_nodes, n_edges);

    scatter_kernel<<<qb, 256>>>(src, dst, n_edges);

    // Join: aggregate needs both branches.
    cudaStreamWaitEvent(0, evGemm, 0);
    int ablocks = (n_nodes * 32 + 255) / 256;      // one warp per node
    aggregate_kernel<<<ablocks, 256>>>(out, n_nodes);
}